// round 2
// baseline (speedup 1.0000x reference)
#include <cuda_runtime.h>
#include <math.h>

// Problem constants (fixed shapes)
#define Tn   4096          // tokens = B*C
#define Dm   1024          // model dim
#define Hm   4096          // hidden dim (4*d)
#define NE   8             // experts
#define CAP  1280          // capacity = floor(2*1.25*4096/8), already even
#define BM   128
#define BN   128
#define BK   16

typedef unsigned long long u64;

// ---------------- scratch (device globals; no allocations allowed) ----------
__device__ int   g_e0[Tn], g_e1[Tn];
__device__ float g_w0[Tn], g_w1[Tn];
__device__ int   g_s0[Tn], g_s1[Tn];
__device__ int   g_tok[NE * CAP];
__device__ int   g_count[NE];
__device__ float g_h [(size_t)NE * CAP * Hm];   // expert hidden (gelu output)
__device__ float g_eo[(size_t)NE * CAP * Dm];   // expert output

// ---------------- packed f32x2 helpers (Blackwell) ---------------------------
__device__ __forceinline__ u64 pack2(float lo, float hi) {
    u64 r; asm("mov.b64 %0, {%1,%2};" : "=l"(r) : "f"(lo), "f"(hi)); return r;
}
__device__ __forceinline__ void unpack2(u64 v, float &lo, float &hi) {
    asm("mov.b64 {%0,%1}, %2;" : "=f"(lo), "=f"(hi) : "l"(v));
}
__device__ __forceinline__ u64 fma2(u64 a, u64 b, u64 c) {
    u64 d; asm("fma.rn.f32x2 %0, %1, %2, %3;" : "=l"(d) : "l"(a), "l"(b), "l"(c));
    return d;
}

// ---------------- router: logits, top-2, softmax over the pair --------------
__global__ void router_kernel(const float* __restrict__ x,
                              const float* __restrict__ wg) {
    int warp = (blockIdx.x * blockDim.x + threadIdx.x) >> 5;
    int lane = threadIdx.x & 31;
    if (warp >= Tn) return;

    const float4* x4 = (const float4*)(x + (size_t)warp * Dm);
    float acc[NE];
#pragma unroll
    for (int e = 0; e < NE; e++) acc[e] = 0.f;

#pragma unroll
    for (int i = 0; i < Dm / 4 / 32; i++) {       // 8 iterations
        float4 v = x4[lane + i * 32];
        int k0 = (lane + i * 32) * 4;
#pragma unroll
        for (int j = 0; j < 4; j++) {
            float xv = (j == 0) ? v.x : (j == 1) ? v.y : (j == 2) ? v.z : v.w;
            float4 wA = *(const float4*)(wg + (size_t)(k0 + j) * NE);
            float4 wB = *(const float4*)(wg + (size_t)(k0 + j) * NE + 4);
            acc[0] += xv * wA.x; acc[1] += xv * wA.y;
            acc[2] += xv * wA.z; acc[3] += xv * wA.w;
            acc[4] += xv * wB.x; acc[5] += xv * wB.y;
            acc[6] += xv * wB.z; acc[7] += xv * wB.w;
        }
    }
#pragma unroll
    for (int off = 16; off; off >>= 1)
#pragma unroll
        for (int e = 0; e < NE; e++)
            acc[e] += __shfl_xor_sync(0xffffffffu, acc[e], off);

    if (lane == 0) {
        int   b0 = 0;  float v0 = acc[0];
        for (int e = 1; e < NE; e++) if (acc[e] > v0) { v0 = acc[e]; b0 = e; }
        int   b1 = -1; float v1 = -INFINITY;
        for (int e = 0; e < NE; e++) if (e != b0 && acc[e] > v1) { v1 = acc[e]; b1 = e; }
        float e1 = expf(v1 - v0);        // v0 >= v1
        float inv = 1.0f / (1.0f + e1);
        g_e0[warp] = b0; g_e1[warp] = b1;
        g_w0[warp] = inv; g_w1[warp] = e1 * inv;
    }
}

// ---------------- exact cumsum ranking + capacity drop (1 warp / expert) ----
__global__ void assign_kernel() {
    int e    = threadIdx.x >> 5;
    int lane = threadIdx.x & 31;
    int base = 0;
    for (int i0 = 0; i0 < 2 * Tn; i0 += 32) {
        int idx = i0 + lane;
        int t   = idx & (Tn - 1);
        int sel = (idx < Tn) ? g_e0[t] : g_e1[t];
        bool mine = (sel == e);
        unsigned bal = __ballot_sync(0xffffffffu, mine);
        int pre = __popc(bal & ((1u << lane) - 1u));
        if (mine) {
            int slot = base + pre;
            int s = (slot < CAP) ? slot : -1;
            if (idx < Tn) g_s0[t] = s; else g_s1[t] = s;
            if (s >= 0) g_tok[e * CAP + s] = t;
        }
        base += __popc(bal);
    }
    int cnt = min(base, CAP);
    if (lane == 0) g_count[e] = cnt;
    for (int s = cnt + lane; s < CAP; s += 32) g_tok[e * CAP + s] = -1;
}

// ---------------- GEMM1: gather(x) @ c_fc[e]  -> gelu -> g_h -----------------
__global__ void __launch_bounds__(256)
gemm1_kernel(const float* __restrict__ x, const float* __restrict__ cfc) {
    const int e    = blockIdx.z;
    const int row0 = blockIdx.y * BM;
    if (row0 >= g_count[e]) return;          // skip empty capacity tiles
    const int nb = blockIdx.x * BN;

    __shared__ __align__(16) float As[BK][BM];
    __shared__ __align__(16) float Bs[BK][BN];

    const int tid = threadIdx.x;
    const int ar  = tid >> 2;
    const int ak  = (tid & 3) << 2;
    const int bkr = tid >> 5;
    const int bn  = (tid & 31) << 2;
    const int ty  = tid >> 4, tx = tid & 15;

    const int tokA = g_tok[e * CAP + row0 + ar];
    const int tokB = g_tok[e * CAP + row0 + ar + 64];
    const float* Bbase = cfc + (size_t)e * Dm * Hm + (size_t)bkr * Hm + nb + bn;

    u64 acc[8][4];
#pragma unroll
    for (int i = 0; i < 8; i++)
#pragma unroll
        for (int j = 0; j < 4; j++) acc[i][j] = 0ull;

    float4 a0 = make_float4(0, 0, 0, 0), a1 = a0, b0, b1;
    if (tokA >= 0) a0 = *(const float4*)(x + (size_t)tokA * Dm + ak);
    if (tokB >= 0) a1 = *(const float4*)(x + (size_t)tokB * Dm + ak);
    b0 = *(const float4*)(Bbase);
    b1 = *(const float4*)(Bbase + (size_t)8 * Hm);

    for (int k0 = 0; k0 < Dm; k0 += BK) {
        __syncthreads();
        As[ak + 0][ar] = a0.x; As[ak + 1][ar] = a0.y;
        As[ak + 2][ar] = a0.z; As[ak + 3][ar] = a0.w;
        As[ak + 0][ar + 64] = a1.x; As[ak + 1][ar + 64] = a1.y;
        As[ak + 2][ar + 64] = a1.z; As[ak + 3][ar + 64] = a1.w;
        *(float4*)&Bs[bkr][bn]     = b0;
        *(float4*)&Bs[bkr + 8][bn] = b1;
        __syncthreads();

        int kn = k0 + BK;
        if (kn < Dm) {                                  // prefetch next tile
            a0 = make_float4(0, 0, 0, 0); a1 = a0;
            if (tokA >= 0) a0 = *(const float4*)(x + (size_t)tokA * Dm + kn + ak);
            if (tokB >= 0) a1 = *(const float4*)(x + (size_t)tokB * Dm + kn + ak);
            b0 = *(const float4*)(Bbase + (size_t)kn * Hm);
            b1 = *(const float4*)(Bbase + (size_t)(kn + 8) * Hm);
        }
#pragma unroll
        for (int kk = 0; kk < BK; kk++) {
            float4 aA = *(const float4*)&As[kk][ty * 8];
            float4 aB = *(const float4*)&As[kk][ty * 8 + 4];
            ulonglong2 bA = *(const ulonglong2*)&Bs[kk][tx * 8];
            ulonglong2 bB = *(const ulonglong2*)&Bs[kk][tx * 8 + 4];
            u64 b2[4] = { bA.x, bA.y, bB.x, bB.y };
            float av[8] = { aA.x, aA.y, aA.z, aA.w, aB.x, aB.y, aB.z, aB.w };
#pragma unroll
            for (int i = 0; i < 8; i++) {
                u64 a2 = pack2(av[i], av[i]);
#pragma unroll
                for (int j = 0; j < 4; j++) acc[i][j] = fma2(a2, b2[j], acc[i][j]);
            }
        }
    }

#pragma unroll
    for (int i = 0; i < 8; i++) {
        float v[8];
#pragma unroll
        for (int j = 0; j < 4; j++) unpack2(acc[i][j], v[2 * j], v[2 * j + 1]);
#pragma unroll
        for (int j = 0; j < 8; j++) {
            float t = v[j];
            v[j] = 0.5f * t * (1.0f + erff(t * 0.70710678118654752440f));
        }
        float* p = g_h + (size_t)(e * CAP + row0 + ty * 8 + i) * Hm + nb + tx * 8;
        *(float4*)p       = make_float4(v[0], v[1], v[2], v[3]);
        *(float4*)(p + 4) = make_float4(v[4], v[5], v[6], v[7]);
    }
}

// ---------------- GEMM2: g_h @ c_proj[e] -> g_eo -----------------------------
__global__ void __launch_bounds__(256)
gemm2_kernel(const float* __restrict__ cproj) {
    const int e    = blockIdx.z;
    const int row0 = blockIdx.y * BM;
    if (row0 >= g_count[e]) return;
    const int nb = blockIdx.x * BN;

    __shared__ __align__(16) float As[BK][BM];
    __shared__ __align__(16) float Bs[BK][BN];

    const int tid = threadIdx.x;
    const int ar  = tid >> 2;
    const int ak  = (tid & 3) << 2;
    const int bkr = tid >> 5;
    const int bn  = (tid & 31) << 2;
    const int ty  = tid >> 4, tx = tid & 15;

    const float* Arow0 = g_h + (size_t)(e * CAP + row0 + ar) * Hm + ak;
    const float* Arow1 = Arow0 + (size_t)64 * Hm;
    const float* Bbase = cproj + (size_t)e * Hm * Dm + (size_t)bkr * Dm + nb + bn;

    u64 acc[8][4];
#pragma unroll
    for (int i = 0; i < 8; i++)
#pragma unroll
        for (int j = 0; j < 4; j++) acc[i][j] = 0ull;

    float4 a0 = *(const float4*)(Arow0);
    float4 a1 = *(const float4*)(Arow1);
    float4 b0 = *(const float4*)(Bbase);
    float4 b1 = *(const float4*)(Bbase + (size_t)8 * Dm);

    for (int k0 = 0; k0 < Hm; k0 += BK) {
        __syncthreads();
        As[ak + 0][ar] = a0.x; As[ak + 1][ar] = a0.y;
        As[ak + 2][ar] = a0.z; As[ak + 3][ar] = a0.w;
        As[ak + 0][ar + 64] = a1.x; As[ak + 1][ar + 64] = a1.y;
        As[ak + 2][ar + 64] = a1.z; As[ak + 3][ar + 64] = a1.w;
        *(float4*)&Bs[bkr][bn]     = b0;
        *(float4*)&Bs[bkr + 8][bn] = b1;
        __syncthreads();

        int kn = k0 + BK;
        if (kn < Hm) {
            a0 = *(const float4*)(Arow0 + kn);
            a1 = *(const float4*)(Arow1 + kn);
            b0 = *(const float4*)(Bbase + (size_t)kn * Dm);
            b1 = *(const float4*)(Bbase + (size_t)(kn + 8) * Dm);
        }
#pragma unroll
        for (int kk = 0; kk < BK; kk++) {
            float4 aA = *(const float4*)&As[kk][ty * 8];
            float4 aB = *(const float4*)&As[kk][ty * 8 + 4];
            ulonglong2 bA = *(const ulonglong2*)&Bs[kk][tx * 8];
            ulonglong2 bB = *(const ulonglong2*)&Bs[kk][tx * 8 + 4];
            u64 b2[4] = { bA.x, bA.y, bB.x, bB.y };
            float av[8] = { aA.x, aA.y, aA.z, aA.w, aB.x, aB.y, aB.z, aB.w };
#pragma unroll
            for (int i = 0; i < 8; i++) {
                u64 a2 = pack2(av[i], av[i]);
#pragma unroll
                for (int j = 0; j < 4; j++) acc[i][j] = fma2(a2, b2[j], acc[i][j]);
            }
        }
    }

#pragma unroll
    for (int i = 0; i < 8; i++) {
        float v[8];
#pragma unroll
        for (int j = 0; j < 4; j++) unpack2(acc[i][j], v[2 * j], v[2 * j + 1]);
        float* p = g_eo + (size_t)(e * CAP + row0 + ty * 8 + i) * Dm + nb + tx * 8;
        *(float4*)p       = make_float4(v[0], v[1], v[2], v[3]);
        *(float4*)(p + 4) = make_float4(v[4], v[5], v[6], v[7]);
    }
}

// ---------------- combine: out[t] = w0*eo[e0,s0] + w1*eo[e1,s1] --------------
__global__ void combine_kernel(float* __restrict__ out) {
    int t = blockIdx.x;
    int c = threadIdx.x * 4;
    int e0 = g_e0[t], e1 = g_e1[t];
    int s0 = g_s0[t], s1 = g_s1[t];
    float w0 = g_w0[t], w1 = g_w1[t];
    float4 r = make_float4(0, 0, 0, 0);
    if (s0 >= 0) {
        float4 v = *(const float4*)(g_eo + (size_t)(e0 * CAP + s0) * Dm + c);
        r.x += w0 * v.x; r.y += w0 * v.y; r.z += w0 * v.z; r.w += w0 * v.w;
    }
    if (s1 >= 0) {
        float4 v = *(const float4*)(g_eo + (size_t)(e1 * CAP + s1) * Dm + c);
        r.x += w1 * v.x; r.y += w1 * v.y; r.z += w1 * v.z; r.w += w1 * v.w;
    }
    *(float4*)(out + (size_t)t * Dm + c) = r;
}

// ---------------- launch -----------------------------------------------------
extern "C" void kernel_launch(void* const* d_in, const int* in_sizes, int n_in,
                              void* d_out, int out_size) {
    const float* x     = (const float*)d_in[0];
    const float* wg    = (const float*)d_in[1];
    const float* cfc   = (const float*)d_in[2];
    const float* cproj = (const float*)d_in[3];
    float* out = (float*)d_out;

    router_kernel<<<Tn / 8, 256>>>(x, wg);      // 8 warps/block, 1 warp/token
    assign_kernel<<<1, 256>>>();
    gemm1_kernel<<<dim3(Hm / BN, CAP / BM, NE), 256>>>(x, cfc);
    gemm2_kernel<<<dim3(Dm / BN, CAP / BM, NE), 256>>>(cproj);
    combine_kernel<<<Tn, 256>>>(out);
}

// round 8
// speedup vs baseline: 1.3887x; 1.3887x over previous
#include <cuda_runtime.h>
#include <cuda_bf16.h>
#include <math.h>
#include <stdint.h>

#define Tn   4096
#define Dm   1024
#define Hm   4096
#define NE   8
#define CAP  1280
#define LDA  34          // A smem row stride (halfs), 128 rows
#define LDB  130         // B smem row stride (halfs), 32 k-rows
#define AH_  0
#define AL_  4352        // 128*34
#define BH_  8704
#define BL_  12864       // 8704 + 32*130
#define SMH  17024       // total halfs (34048 B)

typedef unsigned int u32;
typedef unsigned short u16;

// ---------------- device scratch (same footprint as passing R1) -------------
__device__ int   g_e0[Tn], g_e1[Tn];
__device__ float g_w0[Tn], g_w1[Tn];
__device__ int   g_s0[Tn], g_s1[Tn];
__device__ int   g_tok[NE * CAP];
__device__ int   g_count[NE];
__device__ float g_h [(size_t)NE * CAP * Hm];
__device__ float g_eo[(size_t)NE * CAP * Dm];

// ---------------- helpers ----------------
__device__ __forceinline__ void mma16816(float* d, const u32* a, u32 b0, u32 b1) {
    asm volatile(
        "mma.sync.aligned.m16n8k16.row.col.f32.bf16.bf16.f32 "
        "{%0,%1,%2,%3}, {%4,%5,%6,%7}, {%8,%9}, {%0,%1,%2,%3};"
        : "+f"(d[0]), "+f"(d[1]), "+f"(d[2]), "+f"(d[3])
        : "r"(a[0]), "r"(a[1]), "r"(a[2]), "r"(a[3]), "r"(b0), "r"(b1));
}
__device__ __forceinline__ u32 pack2bf(__nv_bfloat16 a, __nv_bfloat16 b) {
    __nv_bfloat162 t; t.x = a; t.y = b;
    return *reinterpret_cast<u32*>(&t);
}

// ---------------- router (verbatim from passing R1) ----------------
__global__ void router_kernel(const float* __restrict__ x, const float* __restrict__ wg) {
    int warp = (blockIdx.x * blockDim.x + threadIdx.x) >> 5;
    int lane = threadIdx.x & 31;
    if (warp >= Tn) return;
    const float4* x4 = (const float4*)(x + (size_t)warp * Dm);
    float acc[NE];
#pragma unroll
    for (int e = 0; e < NE; e++) acc[e] = 0.f;
#pragma unroll
    for (int i = 0; i < Dm / 128; i++) {
        float4 v = x4[lane + i * 32];
        int k0 = (lane + i * 32) * 4;
#pragma unroll
        for (int j = 0; j < 4; j++) {
            float xv = (j == 0) ? v.x : (j == 1) ? v.y : (j == 2) ? v.z : v.w;
            float4 wA = *(const float4*)(wg + (size_t)(k0 + j) * NE);
            float4 wB = *(const float4*)(wg + (size_t)(k0 + j) * NE + 4);
            acc[0] += xv * wA.x; acc[1] += xv * wA.y; acc[2] += xv * wA.z; acc[3] += xv * wA.w;
            acc[4] += xv * wB.x; acc[5] += xv * wB.y; acc[6] += xv * wB.z; acc[7] += xv * wB.w;
        }
    }
#pragma unroll
    for (int off = 16; off; off >>= 1)
#pragma unroll
        for (int e = 0; e < NE; e++) acc[e] += __shfl_xor_sync(0xffffffffu, acc[e], off);
    if (lane == 0) {
        int b0 = 0; float v0 = acc[0];
        for (int e = 1; e < NE; e++) if (acc[e] > v0) { v0 = acc[e]; b0 = e; }
        int b1 = -1; float v1 = -INFINITY;
        for (int e = 0; e < NE; e++) if (e != b0 && acc[e] > v1) { v1 = acc[e]; b1 = e; }
        float e1 = expf(v1 - v0);
        float inv = 1.0f / (1.0f + e1);
        g_e0[warp] = b0; g_e1[warp] = b1;
        g_w0[warp] = inv; g_w1[warp] = e1 * inv;
    }
}

// ---------------- assignment (verbatim from passing R1) ----------------
__global__ void assign_kernel() {
    int e = threadIdx.x >> 5, lane = threadIdx.x & 31;
    int base = 0;
    for (int i0 = 0; i0 < 2 * Tn; i0 += 32) {
        int idx = i0 + lane;
        int t = idx & (Tn - 1);
        int sel = (idx < Tn) ? g_e0[t] : g_e1[t];
        bool mine = (sel == e);
        unsigned bal = __ballot_sync(0xffffffffu, mine);
        int pre = __popc(bal & ((1u << lane) - 1u));
        if (mine) {
            int slot = base + pre;
            int s = (slot < CAP) ? slot : -1;
            if (idx < Tn) g_s0[t] = s; else g_s1[t] = s;
            if (s >= 0) g_tok[e * CAP + s] = t;
        }
        base += __popc(bal);
    }
    int cnt = min(base, CAP);
    if (lane == 0) g_count[e] = cnt;
    for (int s = cnt + lane; s < CAP; s += 32) g_tok[e * CAP + s] = -1;
}

// ---------------- HMMA GEMM: 128x128 tile, on-the-fly bf16 hi/lo split ------
// A smem: [128 rows][LDA=34 halfs] hi @AH_, lo @AL_
// B smem: [32 k-rows][LDB=130 halfs] hi @BH_, lo @BL_
template <bool IS_G1>
__global__ void __launch_bounds__(256) moe_mma_kernel(const float* __restrict__ xin,
                                                      const float* __restrict__ w) {
    constexpr int KTOT = IS_G1 ? Dm : Hm;
    constexpr int NDIM = IS_G1 ? Hm : Dm;
    constexpr int NCH  = KTOT / 32;

    const int e = blockIdx.z;
    const int row0 = blockIdx.y * 128;
    if (row0 >= g_count[e]) return;
    const int nb = blockIdx.x * 128;

    __shared__ __align__(16) __nv_bfloat16 smh[SMH];
    const int tid = threadIdx.x;

    // ---- producer addressing ----
    const int arow = tid >> 1, kq = (tid & 1) * 16;     // A: 2 thr/row
    const int bkrow = tid >> 3, bng = tid & 7;          // B: 8 thr/k-row
    const float* aPtr;
    bool avalid = true;
    if (IS_G1) {
        int tok = g_tok[e * CAP + row0 + arow];
        avalid = (tok >= 0);
        aPtr = xin + (size_t)(avalid ? tok : 0) * Dm;
    } else {
        aPtr = g_h + (size_t)(e * CAP + row0 + arow) * Hm;
    }
    const float* wPtr = w + (size_t)e * KTOT * NDIM + (size_t)bkrow * NDIM + nb + bng * 16;

    float4 av[4], bv[4];
    #define LOADC(c) do {                                                     \
        const float* pa_ = aPtr + (size_t)(c) * 32 + kq;                      \
        const float* pb_ = wPtr + (size_t)(c) * 32 * NDIM;                    \
        _Pragma("unroll")                                                     \
        for (int j_ = 0; j_ < 4; j_++) {                                      \
            av[j_] = avalid ? *(const float4*)(pa_ + j_ * 4)                  \
                            : make_float4(0.f, 0.f, 0.f, 0.f);                \
            bv[j_] = *(const float4*)(pb_ + j_ * 4);                          \
        }                                                                     \
    } while (0)

    #define STOREC() do {                                                     \
        _Pragma("unroll")                                                     \
        for (int j_ = 0; j_ < 4; j_++) {                                      \
            float f0 = av[j_].x, f1 = av[j_].y, f2 = av[j_].z, f3 = av[j_].w; \
            __nv_bfloat16 h0 = __float2bfloat16(f0), h1 = __float2bfloat16(f1); \
            __nv_bfloat16 h2 = __float2bfloat16(f2), h3 = __float2bfloat16(f3); \
            __nv_bfloat16 l0 = __float2bfloat16(f0 - __bfloat162float(h0));   \
            __nv_bfloat16 l1 = __float2bfloat16(f1 - __bfloat162float(h1));   \
            __nv_bfloat16 l2 = __float2bfloat16(f2 - __bfloat162float(h2));   \
            __nv_bfloat16 l3 = __float2bfloat16(f3 - __bfloat162float(h3));   \
            int ia_ = arow * LDA + kq + j_ * 4;                               \
            *(u32*)&smh[AH_ + ia_]     = pack2bf(h0, h1);                     \
            *(u32*)&smh[AH_ + ia_ + 2] = pack2bf(h2, h3);                     \
            *(u32*)&smh[AL_ + ia_]     = pack2bf(l0, l1);                     \
            *(u32*)&smh[AL_ + ia_ + 2] = pack2bf(l2, l3);                     \
            f0 = bv[j_].x; f1 = bv[j_].y; f2 = bv[j_].z; f3 = bv[j_].w;       \
            h0 = __float2bfloat16(f0); h1 = __float2bfloat16(f1);             \
            h2 = __float2bfloat16(f2); h3 = __float2bfloat16(f3);             \
            l0 = __float2bfloat16(f0 - __bfloat162float(h0));                 \
            l1 = __float2bfloat16(f1 - __bfloat162float(h1));                 \
            l2 = __float2bfloat16(f2 - __bfloat162float(h2));                 \
            l3 = __float2bfloat16(f3 - __bfloat162float(h3));                 \
            int ib_ = bkrow * LDB + bng * 16 + j_ * 4;                        \
            *(u32*)&smh[BH_ + ib_]     = pack2bf(h0, h1);                     \
            *(u32*)&smh[BH_ + ib_ + 2] = pack2bf(h2, h3);                     \
            *(u32*)&smh[BL_ + ib_]     = pack2bf(l0, l1);                     \
            *(u32*)&smh[BL_ + ib_ + 2] = pack2bf(l2, l3);                     \
        }                                                                     \
    } while (0)

    // ---- consumer addressing ----
    const int lane = tid & 31, wid = tid >> 5;
    const int m0 = (wid >> 1) * 32, n0 = (wid & 1) * 64;
    const int g = lane >> 2, c2 = (lane & 3) * 2;

    float acc[2][8][4];
#pragma unroll
    for (int mt = 0; mt < 2; mt++)
#pragma unroll
        for (int nt = 0; nt < 8; nt++)
#pragma unroll
            for (int j = 0; j < 4; j++) acc[mt][nt][j] = 0.f;

    #define LDSU(x) (*reinterpret_cast<const u32*>(&smh[(x)]))
    #define LDSH(x) ((u32)*reinterpret_cast<const u16*>(&smh[(x)]))

    LOADC(0);
#pragma unroll 1
    for (int c = 0; c < NCH; c++) {
        __syncthreads();
        STOREC();
        __syncthreads();
        if (c + 1 < NCH) LOADC(c + 1);

#pragma unroll
        for (int ks = 0; ks < 2; ks++) {
            const int bk = ks * 16;
            u32 ah[2][4], al[2][4];
#pragma unroll
            for (int mt = 0; mt < 2; mt++) {
                int r0 = m0 + mt * 16 + g;
                int i00 = r0 * LDA + bk + c2;
                int i10 = (r0 + 8) * LDA + bk + c2;
                ah[mt][0] = LDSU(AH_ + i00); ah[mt][1] = LDSU(AH_ + i10);
                ah[mt][2] = LDSU(AH_ + i00 + 8); ah[mt][3] = LDSU(AH_ + i10 + 8);
                al[mt][0] = LDSU(AL_ + i00); al[mt][1] = LDSU(AL_ + i10);
                al[mt][2] = LDSU(AL_ + i00 + 8); al[mt][3] = LDSU(AL_ + i10 + 8);
            }
#pragma unroll
            for (int nt = 0; nt < 8; nt++) {
                const int nB = n0 + nt * 8 + g;
                const int rb = (bk + c2) * LDB + nB;
                u32 bh0 = LDSH(BH_ + rb) | (LDSH(BH_ + rb + LDB) << 16);
                u32 bh1 = LDSH(BH_ + rb + 8 * LDB) | (LDSH(BH_ + rb + 9 * LDB) << 16);
                u32 bl0 = LDSH(BL_ + rb) | (LDSH(BL_ + rb + LDB) << 16);
                u32 bl1 = LDSH(BL_ + rb + 8 * LDB) | (LDSH(BL_ + rb + 9 * LDB) << 16);
                mma16816(acc[0][nt], ah[0], bh0, bh1);
                mma16816(acc[1][nt], ah[1], bh0, bh1);
                mma16816(acc[0][nt], al[0], bh0, bh1);
                mma16816(acc[1][nt], al[1], bh0, bh1);
                mma16816(acc[0][nt], ah[0], bl0, bl1);
                mma16816(acc[1][nt], ah[1], bl0, bl1);
            }
        }
    }
    #undef LOADC
    #undef STOREC
    #undef LDSU
    #undef LDSH

    // ---- epilogue ----
    const int tg = lane & 3;
#pragma unroll
    for (int mt = 0; mt < 2; mt++) {
        const int Rb = e * CAP + row0 + m0 + mt * 16 + g;    // rows Rb, Rb+8
#pragma unroll
        for (int nt = 0; nt < 8; nt++) {
            const int col = nb + n0 + nt * 8 + tg * 2;
            float v0 = acc[mt][nt][0], v1 = acc[mt][nt][1];
            float v2 = acc[mt][nt][2], v3 = acc[mt][nt][3];
            if (IS_G1) {
                v0 = 0.5f * v0 * (1.0f + erff(v0 * 0.70710678118654752440f));
                v1 = 0.5f * v1 * (1.0f + erff(v1 * 0.70710678118654752440f));
                v2 = 0.5f * v2 * (1.0f + erff(v2 * 0.70710678118654752440f));
                v3 = 0.5f * v3 * (1.0f + erff(v3 * 0.70710678118654752440f));
                *(float2*)(g_h + (size_t)Rb * Hm + col)       = make_float2(v0, v1);
                *(float2*)(g_h + (size_t)(Rb + 8) * Hm + col) = make_float2(v2, v3);
            } else {
                *(float2*)(g_eo + (size_t)Rb * Dm + col)       = make_float2(v0, v1);
                *(float2*)(g_eo + (size_t)(Rb + 8) * Dm + col) = make_float2(v2, v3);
            }
        }
    }
}

// ---------------- combine (verbatim from passing R1) ----------------
__global__ void combine_kernel(float* __restrict__ out) {
    int t = blockIdx.x;
    int c = threadIdx.x * 4;
    int e0 = g_e0[t], e1 = g_e1[t];
    int s0 = g_s0[t], s1 = g_s1[t];
    float w0 = g_w0[t], w1 = g_w1[t];
    float4 r = make_float4(0, 0, 0, 0);
    if (s0 >= 0) {
        float4 v = *(const float4*)(g_eo + (size_t)(e0 * CAP + s0) * Dm + c);
        r.x += w0 * v.x; r.y += w0 * v.y; r.z += w0 * v.z; r.w += w0 * v.w;
    }
    if (s1 >= 0) {
        float4 v = *(const float4*)(g_eo + (size_t)(e1 * CAP + s1) * Dm + c);
        r.x += w1 * v.x; r.y += w1 * v.y; r.z += w1 * v.z; r.w += w1 * v.w;
    }
    *(float4*)(out + (size_t)t * Dm + c) = r;
}

// ---------------- launch ----------------
extern "C" void kernel_launch(void* const* d_in, const int* in_sizes, int n_in,
                              void* d_out, int out_size) {
    const float* x     = (const float*)d_in[0];
    const float* wg    = (const float*)d_in[1];
    const float* cfc   = (const float*)d_in[2];
    const float* cproj = (const float*)d_in[3];
    float* out = (float*)d_out;

    router_kernel<<<Tn / 8, 256>>>(x, wg);
    assign_kernel<<<1, 256>>>();
    moe_mma_kernel<true><<<dim3(Hm / 128, CAP / 128, NE), 256>>>(x, cfc);
    moe_mma_kernel<false><<<dim3(Dm / 128, CAP / 128, NE), 256>>>(x, cproj);
    combine_kernel<<<Tn, 256>>>(out);
}

// round 9
// speedup vs baseline: 2.3058x; 1.6605x over previous
#include <cuda_runtime.h>
#include <cuda_bf16.h>
#include <math.h>
#include <stdint.h>

#define Tn   4096
#define Dm   1024
#define Hm   4096
#define NE   8
#define CAP  1280
#define LDA  40          // A smem row stride (halfs), 16B-aligned rows
#define LDB  136         // B smem row stride (halfs), 16B-aligned rows
#define AH_  0
#define AL_  5120        // 128*40
#define BH_  10240
#define BL_  14592       // 10240 + 32*136
#define SMH  18944       // total halfs (37888 B, fits static 48K)

typedef unsigned int u32;
typedef unsigned short u16;

// ---------------- device scratch ----------------
__device__ int   g_e0[Tn], g_e1[Tn];
__device__ float g_w0[Tn], g_w1[Tn];
__device__ int   g_s0[Tn], g_s1[Tn];
__device__ int   g_tok[NE * CAP];
__device__ int   g_count[NE];
__device__ float g_h [(size_t)NE * CAP * Hm];
__device__ float g_eo[(size_t)NE * CAP * Dm];

// ---------------- helpers ----------------
__device__ __forceinline__ u32 smem_u32(const void* p) {
    u32 a;
    asm("{ .reg .u64 t; cvta.to.shared.u64 t, %1; cvt.u32.u64 %0, t; }" : "=r"(a) : "l"(p));
    return a;
}
__device__ __forceinline__ void ldsm4(u32* r, u32 a) {
    asm volatile("ldmatrix.sync.aligned.m8n8.x4.shared.b16 {%0,%1,%2,%3}, [%4];"
                 : "=r"(r[0]), "=r"(r[1]), "=r"(r[2]), "=r"(r[3]) : "r"(a));
}
__device__ __forceinline__ void ldsm4t(u32* r, u32 a) {
    asm volatile("ldmatrix.sync.aligned.m8n8.x4.trans.shared.b16 {%0,%1,%2,%3}, [%4];"
                 : "=r"(r[0]), "=r"(r[1]), "=r"(r[2]), "=r"(r[3]) : "r"(a));
}
__device__ __forceinline__ void mma16816(float* d, const u32* a, u32 b0, u32 b1) {
    asm volatile(
        "mma.sync.aligned.m16n8k16.row.col.f32.bf16.bf16.f32 "
        "{%0,%1,%2,%3}, {%4,%5,%6,%7}, {%8,%9}, {%0,%1,%2,%3};"
        : "+f"(d[0]), "+f"(d[1]), "+f"(d[2]), "+f"(d[3])
        : "r"(a[0]), "r"(a[1]), "r"(a[2]), "r"(a[3]), "r"(b0), "r"(b1));
}
__device__ __forceinline__ u32 pack2bf(__nv_bfloat16 a, __nv_bfloat16 b) {
    __nv_bfloat162 t; t.x = a; t.y = b;
    return *reinterpret_cast<u32*>(&t);
}

// ---------------- router (verbatim, passing) ----------------
__global__ void router_kernel(const float* __restrict__ x, const float* __restrict__ wg) {
    int warp = (blockIdx.x * blockDim.x + threadIdx.x) >> 5;
    int lane = threadIdx.x & 31;
    if (warp >= Tn) return;
    const float4* x4 = (const float4*)(x + (size_t)warp * Dm);
    float acc[NE];
#pragma unroll
    for (int e = 0; e < NE; e++) acc[e] = 0.f;
#pragma unroll
    for (int i = 0; i < Dm / 128; i++) {
        float4 v = x4[lane + i * 32];
        int k0 = (lane + i * 32) * 4;
#pragma unroll
        for (int j = 0; j < 4; j++) {
            float xv = (j == 0) ? v.x : (j == 1) ? v.y : (j == 2) ? v.z : v.w;
            float4 wA = *(const float4*)(wg + (size_t)(k0 + j) * NE);
            float4 wB = *(const float4*)(wg + (size_t)(k0 + j) * NE + 4);
            acc[0] += xv * wA.x; acc[1] += xv * wA.y; acc[2] += xv * wA.z; acc[3] += xv * wA.w;
            acc[4] += xv * wB.x; acc[5] += xv * wB.y; acc[6] += xv * wB.z; acc[7] += xv * wB.w;
        }
    }
#pragma unroll
    for (int off = 16; off; off >>= 1)
#pragma unroll
        for (int e = 0; e < NE; e++) acc[e] += __shfl_xor_sync(0xffffffffu, acc[e], off);
    if (lane == 0) {
        int b0 = 0; float v0 = acc[0];
        for (int e = 1; e < NE; e++) if (acc[e] > v0) { v0 = acc[e]; b0 = e; }
        int b1 = -1; float v1 = -INFINITY;
        for (int e = 0; e < NE; e++) if (e != b0 && acc[e] > v1) { v1 = acc[e]; b1 = e; }
        float e1 = expf(v1 - v0);
        float inv = 1.0f / (1.0f + e1);
        g_e0[warp] = b0; g_e1[warp] = b1;
        g_w0[warp] = inv; g_w1[warp] = e1 * inv;
    }
}

// ---------------- assignment (verbatim, passing) ----------------
__global__ void assign_kernel() {
    int e = threadIdx.x >> 5, lane = threadIdx.x & 31;
    int base = 0;
    for (int i0 = 0; i0 < 2 * Tn; i0 += 32) {
        int idx = i0 + lane;
        int t = idx & (Tn - 1);
        int sel = (idx < Tn) ? g_e0[t] : g_e1[t];
        bool mine = (sel == e);
        unsigned bal = __ballot_sync(0xffffffffu, mine);
        int pre = __popc(bal & ((1u << lane) - 1u));
        if (mine) {
            int slot = base + pre;
            int s = (slot < CAP) ? slot : -1;
            if (idx < Tn) g_s0[t] = s; else g_s1[t] = s;
            if (s >= 0) g_tok[e * CAP + s] = t;
        }
        base += __popc(bal);
    }
    int cnt = min(base, CAP);
    if (lane == 0) g_count[e] = cnt;
    for (int s = cnt + lane; s < CAP; s += 32) g_tok[e * CAP + s] = -1;
}

// ---------------- HMMA GEMM: 128x128 tile, ldmatrix fragment feed -----------
template <bool IS_G1>
__global__ void __launch_bounds__(256) moe_mma_kernel(const float* __restrict__ xin,
                                                      const float* __restrict__ w) {
    constexpr int KTOT = IS_G1 ? Dm : Hm;
    constexpr int NDIM = IS_G1 ? Hm : Dm;
    constexpr int NCH  = KTOT / 32;

    const int e = blockIdx.z;
    const int row0 = blockIdx.y * 128;
    if (row0 >= g_count[e]) return;
    const int nb = blockIdx.x * 128;

    __shared__ __align__(16) __nv_bfloat16 smh[SMH];
    const u32 sb = smem_u32(smh);
    const int tid = threadIdx.x;

    // ---- producer addressing (as in passing R8) ----
    const int arow = tid >> 1, kq = (tid & 1) * 16;     // A: 2 thr/row
    const int bkrow = tid >> 3, bng = tid & 7;          // B: 8 thr/k-row
    const float* aPtr;
    bool avalid = true;
    if (IS_G1) {
        int tok = g_tok[e * CAP + row0 + arow];
        avalid = (tok >= 0);
        aPtr = xin + (size_t)(avalid ? tok : 0) * Dm;
    } else {
        aPtr = g_h + (size_t)(e * CAP + row0 + arow) * Hm;
    }
    const float* wPtr = w + (size_t)e * KTOT * NDIM + (size_t)bkrow * NDIM + nb + bng * 16;

    float4 av[4], bv[4];
    #define LOADC(c) do {                                                     \
        const float* pa_ = aPtr + (size_t)(c) * 32 + kq;                      \
        const float* pb_ = wPtr + (size_t)(c) * 32 * NDIM;                    \
        _Pragma("unroll")                                                     \
        for (int j_ = 0; j_ < 4; j_++) {                                      \
            av[j_] = avalid ? *(const float4*)(pa_ + j_ * 4)                  \
                            : make_float4(0.f, 0.f, 0.f, 0.f);                \
            bv[j_] = *(const float4*)(pb_ + j_ * 4);                          \
        }                                                                     \
    } while (0)

    #define STOREC() do {                                                     \
        _Pragma("unroll")                                                     \
        for (int j_ = 0; j_ < 4; j_++) {                                      \
            float f0 = av[j_].x, f1 = av[j_].y, f2 = av[j_].z, f3 = av[j_].w; \
            __nv_bfloat16 h0 = __float2bfloat16(f0), h1 = __float2bfloat16(f1); \
            __nv_bfloat16 h2 = __float2bfloat16(f2), h3 = __float2bfloat16(f3); \
            __nv_bfloat16 l0 = __float2bfloat16(f0 - __bfloat162float(h0));   \
            __nv_bfloat16 l1 = __float2bfloat16(f1 - __bfloat162float(h1));   \
            __nv_bfloat16 l2 = __float2bfloat16(f2 - __bfloat162float(h2));   \
            __nv_bfloat16 l3 = __float2bfloat16(f3 - __bfloat162float(h3));   \
            int ia_ = arow * LDA + kq + j_ * 4;                               \
            *(u32*)&smh[AH_ + ia_]     = pack2bf(h0, h1);                     \
            *(u32*)&smh[AH_ + ia_ + 2] = pack2bf(h2, h3);                     \
            *(u32*)&smh[AL_ + ia_]     = pack2bf(l0, l1);                     \
            *(u32*)&smh[AL_ + ia_ + 2] = pack2bf(l2, l3);                     \
            f0 = bv[j_].x; f1 = bv[j_].y; f2 = bv[j_].z; f3 = bv[j_].w;       \
            h0 = __float2bfloat16(f0); h1 = __float2bfloat16(f1);             \
            h2 = __float2bfloat16(f2); h3 = __float2bfloat16(f3);             \
            l0 = __float2bfloat16(f0 - __bfloat162float(h0));                 \
            l1 = __float2bfloat16(f1 - __bfloat162float(h1));                 \
            l2 = __float2bfloat16(f2 - __bfloat162float(h2));                 \
            l3 = __float2bfloat16(f3 - __bfloat162float(h3));                 \
            int ib_ = bkrow * LDB + bng * 16 + j_ * 4;                        \
            *(u32*)&smh[BH_ + ib_]     = pack2bf(h0, h1);                     \
            *(u32*)&smh[BH_ + ib_ + 2] = pack2bf(h2, h3);                     \
            *(u32*)&smh[BL_ + ib_]     = pack2bf(l0, l1);                     \
            *(u32*)&smh[BL_ + ib_ + 2] = pack2bf(l2, l3);                     \
        }                                                                     \
    } while (0)

    // ---- consumer addressing ----
    const int lane = tid & 31, wid = tid >> 5;
    const int m0 = (wid >> 1) * 32, n0 = (wid & 1) * 64;
    const int g = lane >> 2;

    // ldmatrix lane->address components
    const int aRow = m0 + (lane & 15);                 // + mt*16
    const int aColq = (lane >> 4) * 8;                 // + ks*16
    const int bRowK = (lane & 7) + ((lane & 8) ? 8 : 0);  // + ks*16
    const int bColN = n0 + ((lane & 16) ? 8 : 0);         // + ntp*16

    float acc[2][8][4];
#pragma unroll
    for (int mt = 0; mt < 2; mt++)
#pragma unroll
        for (int nt = 0; nt < 8; nt++)
#pragma unroll
            for (int j = 0; j < 4; j++) acc[mt][nt][j] = 0.f;

    LOADC(0);
#pragma unroll 1
    for (int c = 0; c < NCH; c++) {
        __syncthreads();
        STOREC();
        __syncthreads();
        if (c + 1 < NCH) LOADC(c + 1);

#pragma unroll
        for (int ks = 0; ks < 2; ks++) {
            const int bk = ks * 16;
            u32 ah[2][4], al[2][4];
#pragma unroll
            for (int mt = 0; mt < 2; mt++) {
                const u32 aoff = (u32)((aRow + mt * 16) * LDA + bk + aColq);
                ldsm4(ah[mt], sb + (AH_ + aoff) * 2);
                ldsm4(al[mt], sb + (AL_ + aoff) * 2);
            }
#pragma unroll
            for (int ntp = 0; ntp < 4; ntp++) {
                const u32 boff = (u32)((bk + bRowK) * LDB + bColN + ntp * 16);
                u32 bh[4], bl[4];
                ldsm4t(bh, sb + (BH_ + boff) * 2);
                ldsm4t(bl, sb + (BL_ + boff) * 2);
                const int nt = 2 * ntp;
                mma16816(acc[0][nt],     ah[0], bh[0], bh[1]);
                mma16816(acc[1][nt],     ah[1], bh[0], bh[1]);
                mma16816(acc[0][nt + 1], ah[0], bh[2], bh[3]);
                mma16816(acc[1][nt + 1], ah[1], bh[2], bh[3]);
                mma16816(acc[0][nt],     al[0], bh[0], bh[1]);
                mma16816(acc[1][nt],     al[1], bh[0], bh[1]);
                mma16816(acc[0][nt + 1], al[0], bh[2], bh[3]);
                mma16816(acc[1][nt + 1], al[1], bh[2], bh[3]);
                mma16816(acc[0][nt],     ah[0], bl[0], bl[1]);
                mma16816(acc[1][nt],     ah[1], bl[0], bl[1]);
                mma16816(acc[0][nt + 1], ah[0], bl[2], bl[3]);
                mma16816(acc[1][nt + 1], ah[1], bl[2], bl[3]);
            }
        }
    }
    #undef LOADC
    #undef STOREC

    // ---- epilogue (verbatim from passing R8) ----
    const int tg = lane & 3;
#pragma unroll
    for (int mt = 0; mt < 2; mt++) {
        const int Rb = e * CAP + row0 + m0 + mt * 16 + g;    // rows Rb, Rb+8
#pragma unroll
        for (int nt = 0; nt < 8; nt++) {
            const int col = nb + n0 + nt * 8 + tg * 2;
            float v0 = acc[mt][nt][0], v1 = acc[mt][nt][1];
            float v2 = acc[mt][nt][2], v3 = acc[mt][nt][3];
            if (IS_G1) {
                v0 = 0.5f * v0 * (1.0f + erff(v0 * 0.70710678118654752440f));
                v1 = 0.5f * v1 * (1.0f + erff(v1 * 0.70710678118654752440f));
                v2 = 0.5f * v2 * (1.0f + erff(v2 * 0.70710678118654752440f));
                v3 = 0.5f * v3 * (1.0f + erff(v3 * 0.70710678118654752440f));
                *(float2*)(g_h + (size_t)Rb * Hm + col)       = make_float2(v0, v1);
                *(float2*)(g_h + (size_t)(Rb + 8) * Hm + col) = make_float2(v2, v3);
            } else {
                *(float2*)(g_eo + (size_t)Rb * Dm + col)       = make_float2(v0, v1);
                *(float2*)(g_eo + (size_t)(Rb + 8) * Dm + col) = make_float2(v2, v3);
            }
        }
    }
}

// ---------------- combine (verbatim, passing) ----------------
__global__ void combine_kernel(float* __restrict__ out) {
    int t = blockIdx.x;
    int c = threadIdx.x * 4;
    int e0 = g_e0[t], e1 = g_e1[t];
    int s0 = g_s0[t], s1 = g_s1[t];
    float w0 = g_w0[t], w1 = g_w1[t];
    float4 r = make_float4(0, 0, 0, 0);
    if (s0 >= 0) {
        float4 v = *(const float4*)(g_eo + (size_t)(e0 * CAP + s0) * Dm + c);
        r.x += w0 * v.x; r.y += w0 * v.y; r.z += w0 * v.z; r.w += w0 * v.w;
    }
    if (s1 >= 0) {
        float4 v = *(const float4*)(g_eo + (size_t)(e1 * CAP + s1) * Dm + c);
        r.x += w1 * v.x; r.y += w1 * v.y; r.z += w1 * v.z; r.w += w1 * v.w;
    }
    *(float4*)(out + (size_t)t * Dm + c) = r;
}

// ---------------- launch ----------------
extern "C" void kernel_launch(void* const* d_in, const int* in_sizes, int n_in,
                              void* d_out, int out_size) {
    const float* x     = (const float*)d_in[0];
    const float* wg    = (const float*)d_in[1];
    const float* cfc   = (const float*)d_in[2];
    const float* cproj = (const float*)d_in[3];
    float* out = (float*)d_out;

    router_kernel<<<Tn / 8, 256>>>(x, wg);
    assign_kernel<<<1, 256>>>();
    moe_mma_kernel<true><<<dim3(Hm / 128, CAP / 128, NE), 256>>>(x, cfc);
    moe_mma_kernel<false><<<dim3(Dm / 128, CAP / 128, NE), 256>>>(x, cproj);
    combine_kernel<<<Tn, 256>>>(out);
}